// round 1
// baseline (speedup 1.0000x reference)
#include <cuda_runtime.h>
#include <math_constants.h>

#define DIN  256
#define DOUT 128
#define NMAX 100000
#define EMAX 3200000
#define ALPHA 0.2f

// ---- scratch (static device globals; no allocation) ----
__device__ float g_seq[(size_t)NMAX * DOUT];   // seq_fts = feat @ W
__device__ float g_f1[NMAX];
__device__ float g_f2[NMAX];
__device__ float g_m[NMAX];
__device__ float g_s[NMAX];
__device__ float g_edge[EMAX];                 // logits, then overwritten with e=exp(l-m)

// ---------------------------------------------------------------------------
// float atomic max via sign-split int/uint trick (works for mixed signs,
// init value -inf = 0xFF800000)
__device__ __forceinline__ void atomicMaxFloat(float* addr, float val) {
    if (val >= 0.0f) atomicMax((int*)addr, __float_as_int(val));
    else             atomicMin((unsigned int*)addr, __float_as_uint(val));
}

// ---------------------------------------------------------------------------
// 0) init: out = bias (broadcast), m = -inf, s = 0
__global__ void k_init(float* __restrict__ out, const float* __restrict__ bias, int n) {
    int idx = blockIdx.x * blockDim.x + threadIdx.x;
    if (idx < n * DOUT) out[idx] = bias[idx & (DOUT - 1)];
    if (idx < n) { g_m[idx] = -CUDART_INF_F; g_s[idx] = 0.0f; }
}

// ---------------------------------------------------------------------------
// 1) SGEMM: g_seq[n,128] = feat[n,256] @ W[256,128]
// 128x128 tile, BK=16, 256 threads, 8x8 per thread (cols split 4+4 to cut
// smem bank conflicts).
#define BM 128
#define BN 128
#define BK 16
__global__ __launch_bounds__(256) void k_gemm(const float* __restrict__ A,
                                              const float* __restrict__ W,
                                              int n) {
    __shared__ float As[BK][BM];   // transposed: As[k][m]
    __shared__ float Ws[BK][BN];   // Ws[k][n]
    int tid = threadIdx.x;
    int tx = tid & 15;             // 16 col-groups
    int ty = tid >> 4;             // 16 row-groups
    int rowBase = blockIdx.x * BM;

    float acc[8][8];
    #pragma unroll
    for (int i = 0; i < 8; i++)
        #pragma unroll
        for (int j = 0; j < 8; j++) acc[i][j] = 0.0f;

    for (int k0 = 0; k0 < DIN; k0 += BK) {
        // load A tile: 128 rows x 16 k = 512 float4; 2 per thread
        #pragma unroll
        for (int i = 0; i < 2; i++) {
            int t  = tid + i * 256;        // 0..511
            int m  = t >> 2;               // row in tile
            int kq = (t & 3) * 4;          // k offset (float4)
            int gr = rowBase + m;
            float4 v = make_float4(0.f, 0.f, 0.f, 0.f);
            if (gr < n) v = *(const float4*)(A + (size_t)gr * DIN + k0 + kq);
            As[kq + 0][m] = v.x; As[kq + 1][m] = v.y;
            As[kq + 2][m] = v.z; As[kq + 3][m] = v.w;
        }
        // load W tile: 16 k x 128 cols = 512 float4; 2 per thread
        #pragma unroll
        for (int i = 0; i < 2; i++) {
            int t  = tid + i * 256;
            int kk = t >> 5;               // 0..15
            int nq = (t & 31) * 4;         // 0..124
            *(float4*)&Ws[kk][nq] = *(const float4*)(W + (size_t)(k0 + kk) * DOUT + nq);
        }
        __syncthreads();

        #pragma unroll
        for (int k = 0; k < BK; k++) {
            float ra[8], rb[8];
            #pragma unroll
            for (int i = 0; i < 8; i++) ra[i] = As[k][ty * 8 + i];
            #pragma unroll
            for (int j = 0; j < 4; j++) {
                rb[j]     = Ws[k][tx * 4 + j];
                rb[j + 4] = Ws[k][64 + tx * 4 + j];
            }
            #pragma unroll
            for (int i = 0; i < 8; i++)
                #pragma unroll
                for (int j = 0; j < 8; j++)
                    acc[i][j] += ra[i] * rb[j];
        }
        __syncthreads();
    }

    // store: columns [tx*4, tx*4+4) and [64+tx*4, 64+tx*4+4)
    #pragma unroll
    for (int i = 0; i < 8; i++) {
        int gr = rowBase + ty * 8 + i;
        if (gr < n) {
            float* dst = g_seq + (size_t)gr * DOUT;
            *(float4*)(dst + tx * 4)      = make_float4(acc[i][0], acc[i][1], acc[i][2], acc[i][3]);
            *(float4*)(dst + 64 + tx * 4) = make_float4(acc[i][4], acc[i][5], acc[i][6], acc[i][7]);
        }
    }
}

// ---------------------------------------------------------------------------
// 2) per-node attention scalars: f1 = seq.al_w + al_b, f2 = seq.ar_w + ar_b
// one warp per node, one float4 per lane (32*4 = 128)
__global__ void k_f1f2(const float* __restrict__ al_w, const float* __restrict__ al_b,
                       const float* __restrict__ ar_w, const float* __restrict__ ar_b,
                       int n) {
    int gw   = (blockIdx.x * blockDim.x + threadIdx.x) >> 5;
    int lane = threadIdx.x & 31;
    if (gw >= n) return;
    float4 v = ((const float4*)(g_seq + (size_t)gw * DOUT))[lane];
    float4 a = ((const float4*)al_w)[lane];
    float4 r = ((const float4*)ar_w)[lane];
    float s1 = v.x * a.x + v.y * a.y + v.z * a.z + v.w * a.w;
    float s2 = v.x * r.x + v.y * r.y + v.z * r.z + v.w * r.w;
    #pragma unroll
    for (int o = 16; o > 0; o >>= 1) {
        s1 += __shfl_xor_sync(0xFFFFFFFFu, s1, o);
        s2 += __shfl_xor_sync(0xFFFFFFFFu, s2, o);
    }
    if (lane == 0) {
        g_f1[gw] = s1 + al_b[0];
        g_f2[gw] = s2 + ar_b[0];
    }
}

// ---------------------------------------------------------------------------
// 3) edge logits + segment max
__global__ void k_logits(const int* __restrict__ row, const int* __restrict__ col, int e) {
    int i = blockIdx.x * blockDim.x + threadIdx.x;
    if (i >= e) return;
    int r = row[i], c = col[i];
    float x = g_f1[r] + g_f2[c];
    float l = x > 0.0f ? x : ALPHA * x;
    g_edge[i] = l;
    atomicMaxFloat(&g_m[r], l);
}

// ---------------------------------------------------------------------------
// 4) e = exp(l - m[row]); segment sum
__global__ void k_expsum(const int* __restrict__ row, int e) {
    int i = blockIdx.x * blockDim.x + threadIdx.x;
    if (i >= e) return;
    int r = row[i];
    float ev = __expf(g_edge[i] - g_m[r]);
    g_edge[i] = ev;
    atomicAdd(&g_s[r], ev);
}

// ---------------------------------------------------------------------------
// 5) SpMM scatter: out[row] += (e/s[row]) * seq_fts[col]
// one warp per edge; lane handles one float4 (32*4 = 128); vectorized red.
__global__ __launch_bounds__(256) void k_spmm(const int* __restrict__ row,
                                              const int* __restrict__ col,
                                              float* __restrict__ out, int e) {
    int gw   = (blockIdx.x * blockDim.x + threadIdx.x) >> 5;
    int lane = threadIdx.x & 31;
    if (gw >= e) return;
    int r = row[gw], c = col[gw];
    float coef = g_edge[gw] / g_s[r];
    float4 v = ((const float4*)(g_seq + (size_t)c * DOUT))[lane];
    float* dst = out + (size_t)r * DOUT + lane * 4;
    asm volatile("red.global.add.v4.f32 [%0], {%1, %2, %3, %4};"
                 :: "l"(dst), "f"(v.x * coef), "f"(v.y * coef),
                    "f"(v.z * coef), "f"(v.w * coef)
                 : "memory");
}

// ---------------------------------------------------------------------------
extern "C" void kernel_launch(void* const* d_in, const int* in_sizes, int n_in,
                              void* d_out, int out_size) {
    const float* feat = (const float*)d_in[0];
    const int*   row  = (const int*)  d_in[1];
    const int*   col  = (const int*)  d_in[2];
    const float* W    = (const float*)d_in[3];
    const float* al_w = (const float*)d_in[4];
    const float* al_b = (const float*)d_in[5];
    const float* ar_w = (const float*)d_in[6];
    const float* ar_b = (const float*)d_in[7];
    const float* bias = (const float*)d_in[8];
    float* out = (float*)d_out;

    int n = in_sizes[0] / DIN;   // 100000
    int e = in_sizes[1];         // 3200000

    // 0) init out/m/s
    {
        int total = n * DOUT;
        k_init<<<(total + 255) / 256, 256>>>(out, bias, n);
    }
    // 1) GEMM
    k_gemm<<<(n + BM - 1) / BM, 256>>>(feat, W, n);
    // 2) f1/f2
    k_f1f2<<<(n * 32 + 127) / 128, 128>>>(al_w, al_b, ar_w, ar_b, n);
    // 3) logits + segment max
    k_logits<<<(e + 255) / 256, 256>>>(row, col, e);
    // 4) exp + segment sum
    k_expsum<<<(e + 255) / 256, 256>>>(row, e);
    // 5) softmax-weighted SpMM scatter
    k_spmm<<<(e + 7) / 8, 256>>>(row, col, out, e);
}

// round 2
// speedup vs baseline: 1.7713x; 1.7713x over previous
#include <cuda_runtime.h>
#include <math_constants.h>

#define DIN  256
#define DOUT 128
#define NMAX 100000
#define EMAX 3200000
#define ALPHA 0.2f

// ---- scratch (static device globals; no allocation) ----
__device__ float g_seq[(size_t)NMAX * DOUT];   // seq_fts = feat @ W
__device__ float g_f1[NMAX];
__device__ float g_f2[NMAX];
__device__ float g_s[NMAX];                    // per-row sum of exp(logit)
__device__ int   g_cnt[NMAX];                  // per-row edge count
__device__ int   g_off[NMAX];                  // exclusive prefix (row start)
__device__ int   g_cur[NMAX];                  // scatter cursor; ends as row end
__device__ int   g_bsum[512];                  // scan block partials
__device__ int   g_ecol[EMAX];                 // CSR: col index per edge
__device__ float g_ecoef[EMAX];                // CSR: softmax coef per edge

// ---------------------------------------------------------------------------
// 0) init: s = 0, cnt = 0
__global__ void k_init(int n) {
    int i = blockIdx.x * blockDim.x + threadIdx.x;
    if (i < n) { g_s[i] = 0.0f; g_cnt[i] = 0; }
}

// ---------------------------------------------------------------------------
// 1) SGEMM: g_seq[n,128] = feat[n,256] @ W[256,128]
#define BM 128
#define BN 128
#define BK 16
__global__ __launch_bounds__(256) void k_gemm(const float* __restrict__ A,
                                              const float* __restrict__ W,
                                              int n) {
    __shared__ float As[BK][BM];
    __shared__ float Ws[BK][BN];
    int tid = threadIdx.x;
    int tx = tid & 15;
    int ty = tid >> 4;
    int rowBase = blockIdx.x * BM;

    float acc[8][8];
    #pragma unroll
    for (int i = 0; i < 8; i++)
        #pragma unroll
        for (int j = 0; j < 8; j++) acc[i][j] = 0.0f;

    for (int k0 = 0; k0 < DIN; k0 += BK) {
        #pragma unroll
        for (int i = 0; i < 2; i++) {
            int t  = tid + i * 256;
            int m  = t >> 2;
            int kq = (t & 3) * 4;
            int gr = rowBase + m;
            float4 v = make_float4(0.f, 0.f, 0.f, 0.f);
            if (gr < n) v = *(const float4*)(A + (size_t)gr * DIN + k0 + kq);
            As[kq + 0][m] = v.x; As[kq + 1][m] = v.y;
            As[kq + 2][m] = v.z; As[kq + 3][m] = v.w;
        }
        #pragma unroll
        for (int i = 0; i < 2; i++) {
            int t  = tid + i * 256;
            int kk = t >> 5;
            int nq = (t & 31) * 4;
            *(float4*)&Ws[kk][nq] = *(const float4*)(W + (size_t)(k0 + kk) * DOUT + nq);
        }
        __syncthreads();

        #pragma unroll
        for (int k = 0; k < BK; k++) {
            float ra[8], rb[8];
            #pragma unroll
            for (int i = 0; i < 8; i++) ra[i] = As[k][ty * 8 + i];
            #pragma unroll
            for (int j = 0; j < 4; j++) {
                rb[j]     = Ws[k][tx * 4 + j];
                rb[j + 4] = Ws[k][64 + tx * 4 + j];
            }
            #pragma unroll
            for (int i = 0; i < 8; i++)
                #pragma unroll
                for (int j = 0; j < 8; j++)
                    acc[i][j] += ra[i] * rb[j];
        }
        __syncthreads();
    }

    #pragma unroll
    for (int i = 0; i < 8; i++) {
        int gr = rowBase + ty * 8 + i;
        if (gr < n) {
            float* dst = g_seq + (size_t)gr * DOUT;
            *(float4*)(dst + tx * 4)      = make_float4(acc[i][0], acc[i][1], acc[i][2], acc[i][3]);
            *(float4*)(dst + 64 + tx * 4) = make_float4(acc[i][4], acc[i][5], acc[i][6], acc[i][7]);
        }
    }
}

// ---------------------------------------------------------------------------
// 2) per-node attention scalars
__global__ void k_f1f2(const float* __restrict__ al_w, const float* __restrict__ al_b,
                       const float* __restrict__ ar_w, const float* __restrict__ ar_b,
                       int n) {
    int gw   = (blockIdx.x * blockDim.x + threadIdx.x) >> 5;
    int lane = threadIdx.x & 31;
    if (gw >= n) return;
    float4 v = ((const float4*)(g_seq + (size_t)gw * DOUT))[lane];
    float4 a = ((const float4*)al_w)[lane];
    float4 r = ((const float4*)ar_w)[lane];
    float s1 = v.x * a.x + v.y * a.y + v.z * a.z + v.w * a.w;
    float s2 = v.x * r.x + v.y * r.y + v.z * r.z + v.w * r.w;
    #pragma unroll
    for (int o = 16; o > 0; o >>= 1) {
        s1 += __shfl_xor_sync(0xFFFFFFFFu, s1, o);
        s2 += __shfl_xor_sync(0xFFFFFFFFu, s2, o);
    }
    if (lane == 0) {
        g_f1[gw] = s1 + al_b[0];
        g_f2[gw] = s2 + ar_b[0];
    }
}

// ---------------------------------------------------------------------------
// helper: e = exp(leaky_relu(f1[r] + f2[c]))
__device__ __forceinline__ float edge_exp(int r, int c) {
    float x = g_f1[r] + g_f2[c];
    float l = x > 0.0f ? x : ALPHA * x;
    return __expf(l);
}

// 3) edge pass 1: per-row count + sum of exp (no max needed: logits bounded)
__global__ void k_edge1(const int* __restrict__ row, const int* __restrict__ col, int e) {
    int i = blockIdx.x * blockDim.x + threadIdx.x;
    if (i >= e) return;
    int r = row[i], c = col[i];
    float ev = edge_exp(r, c);
    atomicAdd(&g_s[r], ev);
    atomicAdd(&g_cnt[r], 1);
}

// ---------------------------------------------------------------------------
// 4) 3-kernel exclusive scan over g_cnt -> g_off (+ g_cur copy)
__global__ void k_scan1(int n, int nblk) {
    __shared__ int sh[256];
    int t = threadIdx.x;
    int i = blockIdx.x * 256 + t;
    int v = (i < n) ? g_cnt[i] : 0;
    sh[t] = v;
    __syncthreads();
    #pragma unroll
    for (int o = 1; o < 256; o <<= 1) {
        int x = (t >= o) ? sh[t - o] : 0;
        __syncthreads();
        sh[t] += x;
        __syncthreads();
    }
    if (i < n) g_off[i] = sh[t] - v;          // block-local exclusive
    if (t == 255) g_bsum[blockIdx.x] = sh[255];
}

__global__ void k_scan2(int nblk) {
    __shared__ int sh[512];
    int t = threadIdx.x;
    int v = (t < nblk) ? g_bsum[t] : 0;
    sh[t] = v;
    __syncthreads();
    #pragma unroll
    for (int o = 1; o < 512; o <<= 1) {
        int x = (t >= o) ? sh[t - o] : 0;
        __syncthreads();
        sh[t] += x;
        __syncthreads();
    }
    if (t < nblk) g_bsum[t] = sh[t] - v;      // exclusive over block sums
}

__global__ void k_scan3(int n) {
    int i = blockIdx.x * blockDim.x + threadIdx.x;
    if (i >= n) return;
    int o = g_off[i] + g_bsum[i >> 8];
    g_off[i] = o;
    g_cur[i] = o;
}

// ---------------------------------------------------------------------------
// 5) edge pass 2: scatter into CSR with precomputed coef = e / s[row]
__global__ void k_edge2(const int* __restrict__ row, const int* __restrict__ col, int e) {
    int i = blockIdx.x * blockDim.x + threadIdx.x;
    if (i >= e) return;
    int r = row[i], c = col[i];
    float coef = edge_exp(r, c) / g_s[r];
    int pos = atomicAdd(&g_cur[r], 1);
    g_ecol[pos]  = c;
    g_ecoef[pos] = coef;
}

// ---------------------------------------------------------------------------
// 6) CSR SpMM: one warp per node, register accumulation, single store
__global__ __launch_bounds__(256) void k_spmm(const float* __restrict__ bias,
                                              float* __restrict__ out, int n) {
    int gw   = (blockIdx.x * blockDim.x + threadIdx.x) >> 5;
    int lane = threadIdx.x & 31;
    if (gw >= n) return;
    int j   = g_off[gw];
    int end = g_cur[gw];     // cursor ended at row end

    float4 acc = ((const float4*)bias)[lane];

    for (; j + 2 <= end; j += 2) {
        int   c0 = g_ecol[j],     c1 = g_ecol[j + 1];
        float w0 = g_ecoef[j],    w1 = g_ecoef[j + 1];
        float4 v0 = ((const float4*)(g_seq + (size_t)c0 * DOUT))[lane];
        float4 v1 = ((const float4*)(g_seq + (size_t)c1 * DOUT))[lane];
        acc.x += w0 * v0.x + w1 * v1.x;
        acc.y += w0 * v0.y + w1 * v1.y;
        acc.z += w0 * v0.z + w1 * v1.z;
        acc.w += w0 * v0.w + w1 * v1.w;
    }
    if (j < end) {
        int   c0 = g_ecol[j];
        float w0 = g_ecoef[j];
        float4 v0 = ((const float4*)(g_seq + (size_t)c0 * DOUT))[lane];
        acc.x += w0 * v0.x;
        acc.y += w0 * v0.y;
        acc.z += w0 * v0.z;
        acc.w += w0 * v0.w;
    }
    ((float4*)(out + (size_t)gw * DOUT))[lane] = acc;
}

// ---------------------------------------------------------------------------
extern "C" void kernel_launch(void* const* d_in, const int* in_sizes, int n_in,
                              void* d_out, int out_size) {
    const float* feat = (const float*)d_in[0];
    const int*   row  = (const int*)  d_in[1];
    const int*   col  = (const int*)  d_in[2];
    const float* W    = (const float*)d_in[3];
    const float* al_w = (const float*)d_in[4];
    const float* al_b = (const float*)d_in[5];
    const float* ar_w = (const float*)d_in[6];
    const float* ar_b = (const float*)d_in[7];
    const float* bias = (const float*)d_in[8];
    float* out = (float*)d_out;

    int n = in_sizes[0] / DIN;   // 100000
    int e = in_sizes[1];         // 3200000
    int nblk = (n + 255) / 256;  // scan blocks (<= 512)

    k_init<<<(n + 255) / 256, 256>>>(n);
    k_gemm<<<(n + BM - 1) / BM, 256>>>(feat, W, n);
    k_f1f2<<<(n * 32 + 127) / 128, 128>>>(al_w, al_b, ar_w, ar_b, n);
    k_edge1<<<(e + 255) / 256, 256>>>(row, col, e);
    k_scan1<<<nblk, 256>>>(n, nblk);
    k_scan2<<<1, 512>>>(nblk);
    k_scan3<<<nblk, 256>>>(n);
    k_edge2<<<(e + 255) / 256, 256>>>(row, col, e);
    k_spmm<<<(n * 32 + 255) / 256, 256>>>(bias, out, n);
}